// round 3
// baseline (speedup 1.0000x reference)
#include <cuda_runtime.h>
#include <math.h>

// Problem constants
#define Bc 2
#define Sc 2048
#define Dc 2048
#define Hc 8
#define HDc 256
#define NQ 2048           // H*HD
#define NKV 256           // KVH*HD

// Scratch (device globals -- allocation-free rule)
__device__ float g_Q[(size_t)Bc*Sc*NQ];
__device__ float g_K[(size_t)Bc*Sc*NKV];
__device__ float g_V[(size_t)Bc*Sc*NKV];
__device__ float g_ctx[(size_t)Bc*Sc*NQ];
__device__ float g_attn_fb[(size_t)Bc*Hc*Sc*Sc];

// ---------------------------------------------------------------------------
// Plain NT GEMM: C[M,N] = A[M,K] * B[N,K]^T. 64x64 tile, BK=16, 256 threads,
// 4x4 per thread. Requires M%64==0, N%64==0, K%16==0, 16B-aligned rows.
// ---------------------------------------------------------------------------
__global__ void __launch_bounds__(256)
gemm_nt(const float* __restrict__ A, const float* __restrict__ B,
        float* __restrict__ C, int M, int N, int K, int lda, int ldb, int ldc)
{
    __shared__ float As[16][64];
    __shared__ float Bs[16][64];
    const int m0 = blockIdx.y * 64;
    const int n0 = blockIdx.x * 64;
    const int tid = threadIdx.x;
    const int lrow = tid >> 2;          // 0..63
    const int lk4  = (tid & 3) * 4;     // 0,4,8,12
    const int tx = tid & 15;            // 0..15
    const int ty = tid >> 4;            // 0..15

    float acc[4][4];
#pragma unroll
    for (int i = 0; i < 4; i++)
#pragma unroll
        for (int j = 0; j < 4; j++) acc[i][j] = 0.f;

    for (int k0 = 0; k0 < K; k0 += 16) {
        float4 av = *(const float4*)&A[(size_t)(m0 + lrow) * lda + k0 + lk4];
        As[lk4 + 0][lrow] = av.x;
        As[lk4 + 1][lrow] = av.y;
        As[lk4 + 2][lrow] = av.z;
        As[lk4 + 3][lrow] = av.w;
        float4 bv = *(const float4*)&B[(size_t)(n0 + lrow) * ldb + k0 + lk4];
        Bs[lk4 + 0][lrow] = bv.x;
        Bs[lk4 + 1][lrow] = bv.y;
        Bs[lk4 + 2][lrow] = bv.z;
        Bs[lk4 + 3][lrow] = bv.w;
        __syncthreads();

#pragma unroll
        for (int kk = 0; kk < 16; kk++) {
            float a[4], b[4];
#pragma unroll
            for (int i = 0; i < 4; i++) a[i] = As[kk][ty * 4 + i];
#pragma unroll
            for (int j = 0; j < 4; j++) b[j] = Bs[kk][tx * 4 + j];
#pragma unroll
            for (int i = 0; i < 4; i++)
#pragma unroll
                for (int j = 0; j < 4; j++)
                    acc[i][j] = fmaf(a[i], b[j], acc[i][j]);
        }
        __syncthreads();
    }

#pragma unroll
    for (int i = 0; i < 4; i++)
#pragma unroll
        for (int j = 0; j < 4; j++)
            C[(size_t)(m0 + ty * 4 + i) * ldc + n0 + tx * 4 + j] = acc[i][j];
}

// ---------------------------------------------------------------------------
// RoPE in place. x layout: [(b*S+s), NH*256], pair (d, d+128) per head.
// fp32 angle (matches reference), double-precision sincos for robustness.
// ---------------------------------------------------------------------------
__global__ void rope_kernel(float* __restrict__ x, const int* __restrict__ pos_ids,
                            int NH, long total)
{
    long idx = (long)blockIdx.x * 256 + threadIdx.x;
    if (idx >= total) return;
    int d = (int)(idx & 127);
    long t = idx >> 7;
    int h = (int)(t % NH); t /= NH;
    int s = (int)(t % Sc);
    int b = (int)(t / Sc);

    float p = (float)pos_ids[b * Sc + s];
    float invf = (float)pow(10000.0, -(double)d / 128.0);
    float ang = p * invf;
    double c, sn;
    sincos((double)ang, &sn, &c);
    float cf = (float)c, sf = (float)sn;

    size_t base = ((size_t)(b * Sc + s) * NH + h) * 256;
    float x1 = x[base + d];
    float x2 = x[base + 128 + d];
    x[base + d]       = x1 * cf - x2 * sf;
    x[base + 128 + d] = x2 * cf + x1 * sf;
}

// ---------------------------------------------------------------------------
// scores[z,q,k] = (1/16) * dot(Q[b,q,h,:], K[b,k,:])  for k <= q.
// One block per (q, z=b*H+h). q-vector staged in smem.
// ---------------------------------------------------------------------------
__global__ void __launch_bounds__(256)
scores_kernel(const float* __restrict__ Q, const float* __restrict__ K,
              float* __restrict__ attn)
{
    const int q = blockIdx.x;
    const int z = blockIdx.y;            // b*H + h
    const int b = z >> 3, h = z & 7;
    const int tid = threadIdx.x;

    __shared__ float4 qv[64];
    const float* qrow = Q + ((size_t)(b * Sc + q)) * NQ + h * HDc;
    if (tid < 64) qv[tid] = ((const float4*)qrow)[tid];
    __syncthreads();

    float* arow = attn + ((size_t)z * Sc + q) * Sc;
    for (int k = tid; k <= q; k += 256) {
        const float4* kr = (const float4*)(K + ((size_t)(b * Sc + k)) * NKV);
        float s = 0.f;
#pragma unroll 16
        for (int i = 0; i < 64; i++) {
            float4 kv = kr[i];
            float4 qq = qv[i];
            s = fmaf(qq.x, kv.x, s);
            s = fmaf(qq.y, kv.y, s);
            s = fmaf(qq.z, kv.z, s);
            s = fmaf(qq.w, kv.w, s);
        }
        arow[k] = s * 0.0625f;
    }
}

// ---------------------------------------------------------------------------
// Row softmax with additive mask, in place. One block per row (b,h,q).
// Writes exact 0 for k > q (reference: exp(-1e9 - max) underflows to 0).
// ---------------------------------------------------------------------------
__global__ void __launch_bounds__(256)
softmax_causal_kernel(float* __restrict__ attn, const float* __restrict__ mask)
{
    const int row = blockIdx.x;           // (b*H + h)*S + q
    const int q = row % Sc;
    const int b = row / (Hc * Sc);
    float* p = attn + (size_t)row * Sc;
    const float* mrow = mask + ((size_t)b * Sc + q) * Sc;   // (B,1,S,S)
    const int L = q + 1;
    const int tid = threadIdx.x;

    __shared__ float red[256];
    float vals[8];
    const int nIter = (L + 255) >> 8;     // <= 8

    float m = -1e30f;
#pragma unroll 8
    for (int i = 0; i < nIter; i++) {
        int k = tid + (i << 8);
        float v = (k < L) ? (p[k] + mrow[k]) : -1e30f;
        vals[i] = v;
        m = fmaxf(m, v);
    }
    red[tid] = m;
    __syncthreads();
    for (int s = 128; s > 0; s >>= 1) {
        if (tid < s) red[tid] = fmaxf(red[tid], red[tid + s]);
        __syncthreads();
    }
    m = red[0];
    __syncthreads();

    float sum = 0.f;
#pragma unroll 8
    for (int i = 0; i < nIter; i++) {
        int k = tid + (i << 8);
        float e = (k < L) ? expf(vals[i] - m) : 0.f;
        vals[i] = e;
        sum += e;
    }
    red[tid] = sum;
    __syncthreads();
    for (int s = 128; s > 0; s >>= 1) {
        if (tid < s) red[tid] += red[tid + s];
        __syncthreads();
    }
    float inv = 1.0f / red[0];

#pragma unroll 8
    for (int i = 0; i < nIter; i++) {
        int k = tid + (i << 8);
        if (k < L) p[k] = vals[i] * inv;
    }
    for (int k = L + tid; k < Sc; k += 256) p[k] = 0.f;
}

// ---------------------------------------------------------------------------
// ctx[b,q,h,d] = sum_{k<=q} attn[z,q,k] * V[b,k,d]. One block per (q,z),
// one thread per d. V reads fully coalesced; attn staged via smem.
// ---------------------------------------------------------------------------
__global__ void __launch_bounds__(256)
ctx_kernel(const float* __restrict__ attn, const float* __restrict__ V,
           float* __restrict__ CTX)
{
    const int q = blockIdx.x;
    const int z = blockIdx.y;
    const int b = z >> 3, h = z & 7;
    const int tid = threadIdx.x;

    const float* arow = attn + ((size_t)z * Sc + q) * Sc;
    __shared__ float aw[256];
    float acc = 0.f;

    for (int k0 = 0; k0 <= q; k0 += 256) {
        int kk = k0 + tid;
        aw[tid] = (kk <= q) ? arow[kk] : 0.f;
        __syncthreads();
        const int lim = min(256, q + 1 - k0);
        const float* vp = V + ((size_t)(b * Sc + k0)) * NKV + tid;
#pragma unroll 8
        for (int t = 0; t < lim; t++)
            acc = fmaf(aw[t], vp[(size_t)t * NKV], acc);
        __syncthreads();
    }
    CTX[((size_t)(b * Sc + q)) * NQ + h * HDc + tid] = acc;
}

// ---------------------------------------------------------------------------
extern "C" void kernel_launch(void* const* d_in, const int* in_sizes, int n_in,
                              void* d_out, int out_size)
{
    const float *hidden, *mask, *Wq, *Wk, *Wv, *Wo;
    const int* pos_ids;
    const int POS_E = Bc * Sc;

    if (n_in >= 7 && in_sizes[6] == POS_E) {
        // alphabetical order: Wk, Wo, Wq, Wv, mask, hidden, pos
        Wk      = (const float*)d_in[0];
        Wo      = (const float*)d_in[1];
        Wq      = (const float*)d_in[2];
        Wv      = (const float*)d_in[3];
        mask    = (const float*)d_in[4];
        hidden  = (const float*)d_in[5];
        pos_ids = (const int*)  d_in[6];
    } else {
        // dict/signature order
        hidden  = (const float*)d_in[0];
        mask    = (const float*)d_in[1];
        pos_ids = (const int*)  d_in[2];
        Wq      = (const float*)d_in[3];
        Wk      = (const float*)d_in[4];
        Wv      = (const float*)d_in[5];
        Wo      = (const float*)d_in[6];
    }

    float* out = (float*)d_out;
    const long OUT_E = (long)Bc * Sc * Dc;
    const long ATT_E = (long)Bc * Hc * Sc * Sc;

    float *Q, *K, *V, *CTX, *ATTN_FB;
    cudaGetSymbolAddress((void**)&Q, g_Q);
    cudaGetSymbolAddress((void**)&K, g_K);
    cudaGetSymbolAddress((void**)&V, g_V);
    cudaGetSymbolAddress((void**)&CTX, g_ctx);
    cudaGetSymbolAddress((void**)&ATTN_FB, g_attn_fb);

    float* attn = ((long)out_size >= OUT_E + ATT_E) ? out + OUT_E : ATTN_FB;

    const int MR = Bc * Sc;  // 4096

    // 1) projections
    {
        dim3 g1(NQ / 64, MR / 64);
        gemm_nt<<<g1, 256>>>(hidden, Wq, Q, MR, NQ, Dc, Dc, Dc, NQ);
        dim3 g2(NKV / 64, MR / 64);
        gemm_nt<<<g2, 256>>>(hidden, Wk, K, MR, NKV, Dc, Dc, Dc, NKV);
        gemm_nt<<<g2, 256>>>(hidden, Wv, V, MR, NKV, Dc, Dc, Dc, NKV);
    }
    // 2) RoPE
    {
        long totQ = (long)Bc * Sc * Hc * 128;
        long totK = (long)Bc * Sc * 1 * 128;
        rope_kernel<<<(int)((totQ + 255) / 256), 256>>>(Q, pos_ids, Hc, totQ);
        rope_kernel<<<(int)((totK + 255) / 256), 256>>>(K, pos_ids, 1, totK);
    }
    // 3) scores (causal region only)
    {
        dim3 g(Sc, Bc * Hc);
        scores_kernel<<<g, 256>>>(Q, K, attn);
    }
    // 4) softmax (+ exact zero fill above diagonal)
    {
        softmax_causal_kernel<<<Bc * Hc * Sc, 256>>>(attn, mask);
    }
    // 5) ctx = attn @ V
    {
        dim3 g(Sc, Bc * Hc);
        ctx_kernel<<<g, 256>>>(attn, V, CTX);
    }
    // 6) out = ctx @ Wo^T
    {
        dim3 g(Dc / 64, MR / 64);
        gemm_nt<<<g, 256>>>(CTX, Wo, out, MR, Dc, NQ, NQ, NQ, Dc);
    }
}

// round 4
// speedup vs baseline: 3.3814x; 3.3814x over previous
#include <cuda_runtime.h>
#include <math.h>

// Problem constants
#define Bc 2
#define Sc 2048
#define Dc 2048
#define Hc 8
#define HDc 256
#define NQ 2048           // H*HD
#define NKV 256           // KVH*HD

#define BM 128
#define BN 128
#define BKk 16

// Scratch (device globals -- allocation-free rule)
__device__ float g_Q[(size_t)Bc*Sc*NQ];
__device__ float g_K[(size_t)Bc*Sc*NKV];
__device__ float g_V[(size_t)Bc*Sc*NKV];
__device__ float g_ctx[(size_t)Bc*Sc*NQ];
__device__ float g_attn_fb[(size_t)Bc*Hc*Sc*Sc];

// ---------------------------------------------------------------------------
// 128x128x16 SGEMM, 256 threads, 8x8 per thread.
//   C[m,n] = alpha * sum_k A[m,k] * op(B)
//   TRANSB=true : op(B)[k,n] = B[n,k]   (NT)
//   TRANSB=false: op(B)[k,n] = B[k,n]   (NN)
// CAUSAL: 0 none; 1 skip tiles fully above diagonal; 2 truncate K at m0+BM.
// Batch: z -> (b = z/Hdiv, h = z%Hdiv) with per-operand strides.
// Requires M,N mult of 128; K mult of 16; 16B-aligned bases/lds.
// ---------------------------------------------------------------------------
template<bool TRANSB, int CAUSAL>
__global__ void __launch_bounds__(256)
sgemm128(const float* __restrict__ A, const float* __restrict__ B,
         float* __restrict__ C,
         int M, int N, int K, int lda, int ldb, int ldc,
         long sAb, long sAh, long sBb, long sBh, long sCb, long sCh,
         int Hdiv, float alpha)
{
    const int z = blockIdx.z;
    const int b = z / Hdiv, h = z % Hdiv;
    A += (size_t)b * sAb + (size_t)h * sAh;
    B += (size_t)b * sBb + (size_t)h * sBh;
    C += (size_t)b * sCb + (size_t)h * sCh;

    const int m0 = blockIdx.y * BM;
    const int n0 = blockIdx.x * BN;

    if (CAUSAL == 1 && n0 > m0 + BM - 1) return;     // fully-masked tile

    int kEnd = K;
    if (CAUSAL == 2) kEnd = min(K, m0 + BM);

    __shared__ float As[BKk][BM];
    __shared__ float Bs[BKk][BN];

    const int tid = threadIdx.x;
    const int tx = tid & 15;          // 0..15 (n groups)
    const int ty = tid >> 4;          // 0..15 (m groups)

    const int lrow = tid >> 1;        // 0..127
    const int lk   = (tid & 1) * 8;   // 0 or 8

    const int nrow = tid >> 5;        // 0..7   (NN path)
    const int ncol = (tid & 31) * 4;  // 0..124 (NN path)

    float acc[8][8];
#pragma unroll
    for (int i = 0; i < 8; i++)
#pragma unroll
        for (int j = 0; j < 8; j++) acc[i][j] = 0.f;

    for (int k0 = 0; k0 < kEnd; k0 += BKk) {
        // ---- A tile [BM x BK] -> As[k][m] (transposed store) ----
        {
            const float* ap = &A[(size_t)(m0 + lrow) * lda + k0 + lk];
            float4 a0 = *(const float4*)ap;
            float4 a1 = *(const float4*)(ap + 4);
            As[lk + 0][lrow] = a0.x;  As[lk + 1][lrow] = a0.y;
            As[lk + 2][lrow] = a0.z;  As[lk + 3][lrow] = a0.w;
            As[lk + 4][lrow] = a1.x;  As[lk + 5][lrow] = a1.y;
            As[lk + 6][lrow] = a1.z;  As[lk + 7][lrow] = a1.w;
        }
        // ---- B tile ----
        if (TRANSB) {
            const float* bp = &B[(size_t)(n0 + lrow) * ldb + k0 + lk];
            float4 b0 = *(const float4*)bp;
            float4 b1 = *(const float4*)(bp + 4);
            Bs[lk + 0][lrow] = b0.x;  Bs[lk + 1][lrow] = b0.y;
            Bs[lk + 2][lrow] = b0.z;  Bs[lk + 3][lrow] = b0.w;
            Bs[lk + 4][lrow] = b1.x;  Bs[lk + 5][lrow] = b1.y;
            Bs[lk + 6][lrow] = b1.z;  Bs[lk + 7][lrow] = b1.w;
        } else {
            float4 b0 = *(const float4*)&B[(size_t)(k0 + nrow) * ldb + n0 + ncol];
            float4 b1 = *(const float4*)&B[(size_t)(k0 + nrow + 8) * ldb + n0 + ncol];
            *(float4*)&Bs[nrow][ncol]     = b0;
            *(float4*)&Bs[nrow + 8][ncol] = b1;
        }
        __syncthreads();

#pragma unroll
        for (int kk = 0; kk < BKk; kk++) {
            float4 a0 = *(const float4*)&As[kk][ty * 8];
            float4 a1 = *(const float4*)&As[kk][ty * 8 + 4];
            float4 b0 = *(const float4*)&Bs[kk][tx * 8];
            float4 b1 = *(const float4*)&Bs[kk][tx * 8 + 4];
            float ar[8] = {a0.x, a0.y, a0.z, a0.w, a1.x, a1.y, a1.z, a1.w};
            float br[8] = {b0.x, b0.y, b0.z, b0.w, b1.x, b1.y, b1.z, b1.w};
#pragma unroll
            for (int i = 0; i < 8; i++)
#pragma unroll
                for (int j = 0; j < 8; j++)
                    acc[i][j] = fmaf(ar[i], br[j], acc[i][j]);
        }
        __syncthreads();
    }

#pragma unroll
    for (int i = 0; i < 8; i++) {
        size_t row = (size_t)(m0 + ty * 8 + i);
        float4 v0 = {alpha * acc[i][0], alpha * acc[i][1],
                     alpha * acc[i][2], alpha * acc[i][3]};
        float4 v1 = {alpha * acc[i][4], alpha * acc[i][5],
                     alpha * acc[i][6], alpha * acc[i][7]};
        *(float4*)&C[row * ldc + n0 + tx * 8]     = v0;
        *(float4*)&C[row * ldc + n0 + tx * 8 + 4] = v1;
    }
}

// ---------------------------------------------------------------------------
// RoPE in place. Fast + fast-math-proof: fp32 inv_freq via exp2f (matches
// reference fp32 compute), exact double angle, manual 2*pi reduction, sincosf
// on reduced angle (|r| <= pi, accurate even under --use_fast_math).
// ---------------------------------------------------------------------------
__global__ void rope_kernel(float* __restrict__ x, const int* __restrict__ pos_ids,
                            int NH, long total)
{
    long idx = (long)blockIdx.x * 256 + threadIdx.x;
    if (idx >= total) return;
    int d = (int)(idx & 127);
    long t = idx >> 7;
    int h = (int)(t % NH); t /= NH;
    int s = (int)(t % Sc);
    int b = (int)(t / Sc);

    float p = (float)pos_ids[b * Sc + s];
    // 10000^(-d/128) = 2^(-d * log2(10000)/128)
    float invf = exp2f(-0.103810252965736f * (float)d);
    double ang = (double)p * (double)invf;
    double kq = nearbyint(ang * 0.15915494309189535);   // /(2*pi)
    float r = (float)(ang - kq * 6.283185307179586);
    float sn, c;
    sincosf(r, &sn, &c);

    size_t base = ((size_t)(b * Sc + s) * NH + h) * 256;
    float x1 = x[base + d];
    float x2 = x[base + 128 + d];
    x[base + d]       = x1 * c - x2 * sn;
    x[base + 128 + d] = x2 * c + x1 * sn;
}

// ---------------------------------------------------------------------------
// Row softmax with additive mask, in place. One block per row (b,h,q).
// Writes exact 0 for k > q (reference: exp(-1e9 - max) underflows to 0).
// ---------------------------------------------------------------------------
__global__ void __launch_bounds__(256)
softmax_causal_kernel(float* __restrict__ attn, const float* __restrict__ mask)
{
    const int row = blockIdx.x;           // (b*H + h)*S + q
    const int q = row % Sc;
    const int b = row / (Hc * Sc);
    float* p = attn + (size_t)row * Sc;
    const float* mrow = mask + ((size_t)b * Sc + q) * Sc;   // (B,1,S,S)
    const int L = q + 1;
    const int tid = threadIdx.x;

    __shared__ float red[256];
    float vals[8];
    const int nIter = (L + 255) >> 8;     // <= 8

    float m = -1e30f;
#pragma unroll 8
    for (int i = 0; i < nIter; i++) {
        int k = tid + (i << 8);
        float v = (k < L) ? (p[k] + mrow[k]) : -1e30f;
        vals[i] = v;
        m = fmaxf(m, v);
    }
    red[tid] = m;
    __syncthreads();
    for (int s = 128; s > 0; s >>= 1) {
        if (tid < s) red[tid] = fmaxf(red[tid], red[tid + s]);
        __syncthreads();
    }
    m = red[0];
    __syncthreads();

    float sum = 0.f;
#pragma unroll 8
    for (int i = 0; i < nIter; i++) {
        int k = tid + (i << 8);
        float e = (k < L) ? expf(vals[i] - m) : 0.f;
        vals[i] = e;
        sum += e;
    }
    red[tid] = sum;
    __syncthreads();
    for (int s = 128; s > 0; s >>= 1) {
        if (tid < s) red[tid] += red[tid + s];
        __syncthreads();
    }
    float inv = 1.0f / red[0];

#pragma unroll 8
    for (int i = 0; i < nIter; i++) {
        int k = tid + (i << 8);
        if (k < L) p[k] = vals[i] * inv;
    }
    for (int k = L + tid; k < Sc; k += 256) p[k] = 0.f;
}

// ---------------------------------------------------------------------------
extern "C" void kernel_launch(void* const* d_in, const int* in_sizes, int n_in,
                              void* d_out, int out_size)
{
    const float *hidden, *mask, *Wq, *Wk, *Wv, *Wo;
    const int* pos_ids;
    const int POS_E = Bc * Sc;

    if (n_in >= 7 && in_sizes[6] == POS_E) {
        Wk      = (const float*)d_in[0];
        Wo      = (const float*)d_in[1];
        Wq      = (const float*)d_in[2];
        Wv      = (const float*)d_in[3];
        mask    = (const float*)d_in[4];
        hidden  = (const float*)d_in[5];
        pos_ids = (const int*)  d_in[6];
    } else {
        hidden  = (const float*)d_in[0];
        mask    = (const float*)d_in[1];
        pos_ids = (const int*)  d_in[2];
        Wq      = (const float*)d_in[3];
        Wk      = (const float*)d_in[4];
        Wv      = (const float*)d_in[5];
        Wo      = (const float*)d_in[6];
    }

    float* out = (float*)d_out;
    const long OUT_E = (long)Bc * Sc * Dc;
    const long ATT_E = (long)Bc * Hc * Sc * Sc;

    float *Q, *K, *V, *CTX, *ATTN_FB;
    cudaGetSymbolAddress((void**)&Q, g_Q);
    cudaGetSymbolAddress((void**)&K, g_K);
    cudaGetSymbolAddress((void**)&V, g_V);
    cudaGetSymbolAddress((void**)&CTX, g_ctx);
    cudaGetSymbolAddress((void**)&ATTN_FB, g_attn_fb);

    float* attn = ((long)out_size >= OUT_E + ATT_E) ? out + OUT_E : ATTN_FB;

    const int MR = Bc * Sc;  // 4096

    // 1) projections (NT)
    {
        dim3 gq(NQ / BN, MR / BM, 1);
        sgemm128<true, 0><<<gq, 256>>>(hidden, Wq, Q, MR, NQ, Dc, Dc, Dc, NQ,
                                       0, 0, 0, 0, 0, 0, 1, 1.0f);
        dim3 gkv(NKV / BN, MR / BM, 1);
        sgemm128<true, 0><<<gkv, 256>>>(hidden, Wk, K, MR, NKV, Dc, Dc, Dc, NKV,
                                        0, 0, 0, 0, 0, 0, 1, 1.0f);
        sgemm128<true, 0><<<gkv, 256>>>(hidden, Wv, V, MR, NKV, Dc, Dc, Dc, NKV,
                                        0, 0, 0, 0, 0, 0, 1, 1.0f);
    }
    // 2) RoPE
    {
        long totQ = (long)Bc * Sc * Hc * 128;
        long totK = (long)Bc * Sc * 1 * 128;
        rope_kernel<<<(int)((totQ + 255) / 256), 256>>>(Q, pos_ids, Hc, totQ);
        rope_kernel<<<(int)((totK + 255) / 256), 256>>>(K, pos_ids, 1, totK);
    }
    // 3) scores = (1/16) Q K^T, causal tile-skip  (NT, batched over z=b*8+h)
    {
        dim3 g(Sc / BN, Sc / BM, Bc * Hc);
        sgemm128<true, 1><<<g, 256>>>(
            Q, K, attn, Sc, Sc, HDc,
            NQ, NKV, Sc,
            (long)Sc * NQ, (long)HDc,          // A: Q
            (long)Sc * NKV, 0,                 // B: K (shared across heads)
            (long)Hc * Sc * Sc, (long)Sc * Sc, // C: attn
            Hc, 1.0f / 16.0f);
    }
    // 4) softmax (+ exact zero fill above diagonal)
    {
        softmax_causal_kernel<<<Bc * Hc * Sc, 256>>>(attn, mask);
    }
    // 5) ctx = attn @ V (NN, k-loop truncated at q-tile end)
    {
        dim3 g(NKV / BN, Sc / BM, Bc * Hc);
        sgemm128<false, 2><<<g, 256>>>(
            attn, V, CTX, Sc, NKV, Sc,
            Sc, NKV, NQ,
            (long)Hc * Sc * Sc, (long)Sc * Sc, // A: attn
            (long)Sc * NKV, 0,                 // B: V (shared across heads)
            (long)Sc * NQ, (long)HDc,          // C: ctx
            Hc, 1.0f);
    }
    // 6) out = ctx @ Wo^T (NT)
    {
        dim3 g(Dc / BN, MR / BM, 1);
        sgemm128<true, 0><<<g, 256>>>(CTX, Wo, out, MR, Dc, NQ, NQ, NQ, Dc,
                                      0, 0, 0, 0, 0, 0, 1, 1.0f);
    }
}